// round 2
// baseline (speedup 1.0000x reference)
#include <cuda_runtime.h>
#include <cuda_fp16.h>
#include <cstdint>
#include <cstddef>

// ---------------------------------------------------------------------------
// Problem dims (fixed by the dataset)
// ---------------------------------------------------------------------------
#define T_TOK 16384           // 16 * 1024 tokens
#define H_DIM 1152            // K
#define O_DIM 4608            // N

// ---------------------------------------------------------------------------
// GEMM tiling (sm_80-style mma.sync pipeline; tcgen05 unusable: harness builds
// through a plain compute_103 PTX target which rejects tcgen05)
// ---------------------------------------------------------------------------
#define BM 128
#define BN 128
#define BK 32                 // 32 halves = 64 B per row
#define NSTAGES 4
#define KITERS (H_DIM / BK)   // 36
#define TILE_BYTES (BM * BK * 2)            // 8192 (A), same for B
#define STAGE_BYTES (2 * TILE_BYTES)        // 16384
#define SMEM_TOTAL (NSTAGES * STAGE_BYTES)  // 65536

// SW128-style XOR swizzle on linear byte offsets (64B rows -> 128B period)
#define SWZ(o) ((o) ^ (((o) >> 3) & 0x70))

// ---------------------------------------------------------------------------
// Scratch (device globals: no runtime allocation allowed)
// ---------------------------------------------------------------------------
__device__ __align__(1024) __half g_A[(size_t)T_TOK * H_DIM];  // quantized acts
__device__ __align__(1024) __half g_W[(size_t)O_DIM * H_DIM];  // fp16 weights

// ---------------------------------------------------------------------------
// PTX helpers (all sm_80-era, safe under compute_103)
// ---------------------------------------------------------------------------
__device__ __forceinline__ uint32_t smem_u32(const void* p) {
    return (uint32_t)__cvta_generic_to_shared(p);
}

#define CP_ASYNC16(dst, src) \
    asm volatile("cp.async.cg.shared.global [%0], [%1], 16;" :: "r"(dst), "l"(src))
#define CP_ASYNC_COMMIT() asm volatile("cp.async.commit_group;" ::: "memory")
#define CP_ASYNC_WAIT(n)  asm volatile("cp.async.wait_group %0;" :: "n"(n) : "memory")

__device__ __forceinline__ void ldsm_x4(uint32_t& r0, uint32_t& r1, uint32_t& r2,
                                        uint32_t& r3, uint32_t addr) {
    asm volatile("ldmatrix.sync.aligned.m8n8.x4.shared.b16 {%0,%1,%2,%3}, [%4];"
                 : "=r"(r0), "=r"(r1), "=r"(r2), "=r"(r3) : "r"(addr));
}

__device__ __forceinline__ void mma16816(float& d0, float& d1, float& d2, float& d3,
                                         uint32_t a0, uint32_t a1, uint32_t a2,
                                         uint32_t a3, uint32_t b0, uint32_t b1) {
    asm volatile(
        "mma.sync.aligned.m16n8k16.row.col.f32.f16.f16.f32 "
        "{%0,%1,%2,%3}, {%4,%5,%6,%7}, {%8,%9}, {%0,%1,%2,%3};"
        : "+f"(d0), "+f"(d1), "+f"(d2), "+f"(d3)
        : "r"(a0), "r"(a1), "r"(a2), "r"(a3), "r"(b0), "r"(b1));
}

// ---------------------------------------------------------------------------
// Kernel 1: SmoothQuant + per-token prescale + NVFP4 fake-quant -> fp16 A
// fp32 ops replicate the reference order exactly (rn intrinsics, no FMA).
// ---------------------------------------------------------------------------
__global__ void __launch_bounds__(128) quant_kernel(const float* __restrict__ x,
                                                    const float* __restrict__ smooth) {
    const int t = blockIdx.x;
    const int tid = threadIdx.x;
    const float* xrow = x + (size_t)t * H_DIM;

    float v[9];
    float tm = 0.0f;
#pragma unroll
    for (int s = 0; s < 9; s++) {
        int h = tid + 128 * s;
        v[s] = __fmul_rn(__ldg(xrow + h), __ldg(smooth + h));
        tm = fmaxf(tm, fabsf(v[s]));
    }
#pragma unroll
    for (int off = 16; off; off >>= 1)
        tm = fmaxf(tm, __shfl_xor_sync(0xffffffffu, tm, off));
    __shared__ float red[4];
    if ((tid & 31) == 0) red[tid >> 5] = tm;
    __syncthreads();
    tm = fmaxf(fmaxf(red[0], red[1]), fmaxf(red[2], red[3]));
    tm = fmaxf(tm, 1e-12f);                 // clip
    const float pre = __fdiv_rn(tm, 6.0f);  // pre_scale

    __half* arow = g_A + (size_t)t * H_DIM;
#pragma unroll
    for (int s = 0; s < 9; s++) {
        float xp = __fdiv_rn(v[s], pre);    // x_pre
        float a = fabsf(xp);
        float am = a;
        // block of 16 contiguous h == 16 consecutive lanes at this s
#pragma unroll
        for (int off = 8; off; off >>= 1)
            am = fmaxf(am, __shfl_xor_sync(0xffffffffu, am, off));
        am = fmaxf(am, 1e-12f);
        float scale = __fdiv_rn(am, 6.0f);
        float n = __fdiv_rn(a, scale);
        // argmin over NVFP4 levels; ties go to the LOWER level (argmin first-index)
        float level = (n <= 0.25f) ? 0.0f :
                      (n <= 0.75f) ? 0.5f :
                      (n <= 1.25f) ? 1.0f :
                      (n <= 1.75f) ? 1.5f :
                      (n <= 2.5f)  ? 2.0f :
                      (n <= 3.5f)  ? 3.0f :
                      (n <= 5.0f)  ? 4.0f : 6.0f;
        float sgn = (xp > 0.0f) ? 1.0f : ((xp < 0.0f) ? -1.0f : xp);
        float q = __fmul_rn(__fmul_rn(__fmul_rn(sgn, level), scale), pre);
        arow[tid + 128 * s] = __float2half_rn(q);
    }
}

// ---------------------------------------------------------------------------
// Kernel 2: W fp32 -> fp16
// ---------------------------------------------------------------------------
__global__ void __launch_bounds__(256) wconv_kernel(const float* __restrict__ w) {
    int i = (blockIdx.x * 256 + threadIdx.x) * 4;
    if (i < O_DIM * H_DIM) {
        float4 f = *reinterpret_cast<const float4*>(w + i);
        __half2* p = reinterpret_cast<__half2*>(g_W + i);
        p[0] = __floats2half2_rn(f.x, f.y);
        p[1] = __floats2half2_rn(f.z, f.w);
    }
}

// ---------------------------------------------------------------------------
// Kernel 3: fp16 mma.sync GEMM   out[m,n] = sum_k A[m,k]*W[n,k] + bias[n]
// ---------------------------------------------------------------------------
__device__ __forceinline__ void load_stage(uint32_t sbase, int st, int kt,
                                           int m0, int n0, int tid) {
    const uint32_t sA = sbase + st * STAGE_BYTES;
    const uint32_t sB = sA + TILE_BYTES;
    const __half* Ag = g_A + (size_t)m0 * H_DIM + kt * BK;
    const __half* Bg = g_W + (size_t)n0 * H_DIM + kt * BK;
#pragma unroll
    for (int i = 0; i < 2; i++) {          // A: 512 x 16B chunks
        int g = tid + i * 256;
        int r = g >> 2, c = g & 3;
        uint32_t off = SWZ((uint32_t)(r * 64 + c * 16));
        CP_ASYNC16(sA + off, Ag + (size_t)r * H_DIM + c * 8);
    }
#pragma unroll
    for (int i = 0; i < 2; i++) {          // B: 512 x 16B chunks
        int g = tid + i * 256;
        int r = g >> 2, c = g & 3;
        uint32_t off = SWZ((uint32_t)(r * 64 + c * 16));
        CP_ASYNC16(sB + off, Bg + (size_t)r * H_DIM + c * 8);
    }
}

__global__ void __launch_bounds__(256, 2) gemm_kernel(const float* __restrict__ bias,
                                                      float* __restrict__ out) {
    extern __shared__ char smem[];
    const uint32_t sbase = smem_u32(smem);
    const int tid = threadIdx.x;
    const int wid = tid >> 5;
    const int lid = tid & 31;
    const int wm = wid & 1;        // 2 warp rows  (64 M each)
    const int wn = wid >> 1;       // 4 warp cols  (32 N each)
    const int m0 = blockIdx.y * BM;
    const int n0 = blockIdx.x * BN;

    float acc[4][4][4];
#pragma unroll
    for (int i = 0; i < 4; i++)
#pragma unroll
        for (int j = 0; j < 4; j++)
#pragma unroll
            for (int e = 0; e < 4; e++) acc[i][j][e] = 0.0f;

    // Per-lane ldmatrix base offsets (bytes within a tile)
    // A (.x4): lane l -> row m0w + (l&15), k-chunk (l>>4)
    const uint32_t a_row = (uint32_t)(wm * 64 + (lid & 15)) * 64;
    const uint32_t a_ch  = (uint32_t)(lid >> 4) * 16;
    // B (.x4 covering 16 n rows): lane l -> n row wn*32 + p*16 + ((l>>3)&2)*4 + (l&7),
    //                             k-chunk ((l>>3)&1)
    const uint32_t b_row = (uint32_t)(wn * 32 + ((lid >> 3) & 2) * 4 + (lid & 7)) * 64;
    const uint32_t b_ch  = (uint32_t)((lid >> 3) & 1) * 16;

    // prologue
#pragma unroll
    for (int p = 0; p < NSTAGES - 1; p++) {
        load_stage(sbase, p, p, m0, n0, tid);
        CP_ASYNC_COMMIT();
    }

    for (int kt = 0; kt < KITERS; kt++) {
        const int st = kt & (NSTAGES - 1);
        CP_ASYNC_WAIT(NSTAGES - 2);
        __syncthreads();

        // refill stage (kt+3)&3 == (kt-1)&3 (its readers finished before this barrier)
        const int nk = kt + NSTAGES - 1;
        if (nk < KITERS) load_stage(sbase, nk & (NSTAGES - 1), nk, m0, n0, tid);
        CP_ASYNC_COMMIT();

        const uint32_t sA = sbase + st * STAGE_BYTES;
        const uint32_t sB = sA + TILE_BYTES;
#pragma unroll
        for (int ks = 0; ks < 2; ks++) {   // two k16 steps per BK=32
            uint32_t a[4][4];
#pragma unroll
            for (int mi = 0; mi < 4; mi++) {
                uint32_t o = a_row + (uint32_t)mi * (16 * 64) + (a_ch + ks * 32);
                ldsm_x4(a[mi][0], a[mi][1], a[mi][2], a[mi][3], sA + SWZ(o));
            }
            uint32_t b[4][2];
#pragma unroll
            for (int p = 0; p < 2; p++) {  // each covers n-frags 2p, 2p+1
                uint32_t o = b_row + (uint32_t)p * (16 * 64) + (b_ch + ks * 32);
                uint32_t r0, r1, r2, r3;
                ldsm_x4(r0, r1, r2, r3, sB + SWZ(o));
                b[2 * p][0] = r0; b[2 * p][1] = r1;
                b[2 * p + 1][0] = r2; b[2 * p + 1][1] = r3;
            }
#pragma unroll
            for (int mi = 0; mi < 4; mi++)
#pragma unroll
                for (int ni = 0; ni < 4; ni++)
                    mma16816(acc[mi][ni][0], acc[mi][ni][1],
                             acc[mi][ni][2], acc[mi][ni][3],
                             a[mi][0], a[mi][1], a[mi][2], a[mi][3],
                             b[ni][0], b[ni][1]);
        }
    }

    // epilogue: fused bias, fp32 stores
    const int tr = lid >> 2;       // 0..7
    const int tc = lid & 3;        // 0..3
    const int mb = m0 + wm * 64;
    const int nb = n0 + wn * 32;
    float2 bv[4];
#pragma unroll
    for (int ni = 0; ni < 4; ni++)
        bv[ni] = *reinterpret_cast<const float2*>(bias + nb + ni * 8 + tc * 2);
#pragma unroll
    for (int mi = 0; mi < 4; mi++) {
        float* r0 = out + (size_t)(mb + mi * 16 + tr) * O_DIM + nb;
        float* r1 = r0 + (size_t)8 * O_DIM;
#pragma unroll
        for (int ni = 0; ni < 4; ni++) {
            float2 v0, v1;
            v0.x = acc[mi][ni][0] + bv[ni].x;
            v0.y = acc[mi][ni][1] + bv[ni].y;
            v1.x = acc[mi][ni][2] + bv[ni].x;
            v1.y = acc[mi][ni][3] + bv[ni].y;
            *reinterpret_cast<float2*>(r0 + ni * 8 + tc * 2) = v0;
            *reinterpret_cast<float2*>(r1 + ni * 8 + tc * 2) = v1;
        }
    }
}

// ---------------------------------------------------------------------------
// Launch
// ---------------------------------------------------------------------------
extern "C" void kernel_launch(void* const* d_in, const int* in_sizes, int n_in,
                              void* d_out, int out_size) {
    const float* x      = (const float*)d_in[0];  // [16,1024,1152]
    const float* w      = (const float*)d_in[1];  // [4608,1152]
    const float* smooth = (const float*)d_in[2];  // [1152]
    const float* bias   = (const float*)d_in[3];  // [4608]
    float* out = (float*)d_out;                   // [16,1024,4608]

    quant_kernel<<<T_TOK, 128>>>(x, smooth);
    wconv_kernel<<<(O_DIM * H_DIM / 4 + 255) / 256, 256>>>(w);

    cudaFuncSetAttribute(gemm_kernel, cudaFuncAttributeMaxDynamicSharedMemorySize,
                         SMEM_TOTAL);
    dim3 grid(O_DIM / BN, T_TOK / BM);   // (36, 128)
    gemm_kernel<<<grid, 256, SMEM_TOTAL>>>(bias, out);
}